// round 2
// baseline (speedup 1.0000x reference)
#include <cuda_runtime.h>

#define NROWS    16384
#define DIM      4096
#define NEXP     64
#define KB       32
#define ROWS_CTA 128
#define NTHREADS 256
#define NCHUNK   (DIM / KB)

typedef unsigned long long u64;

__device__ __forceinline__ u64 fma2(u64 a, u64 b, u64 c) {
    u64 d;
    asm("fma.rn.f32x2 %0, %1, %2, %3;" : "=l"(d) : "l"(a), "l"(b), "l"(c));
    return d;
}
__device__ __forceinline__ u64 add2(u64 a, u64 b) {
    u64 d;
    asm("add.rn.f32x2 %0, %1, %2;" : "=l"(d) : "l"(a), "l"(b));
    return d;
}
__device__ __forceinline__ u64 dup2(float v) {
    u64 d;
    asm("mov.b64 %0, {%1, %1};" : "=l"(d) : "f"(v));
    return d;
}
__device__ __forceinline__ void unpack2(u64 v, float& lo, float& hi) {
    asm("mov.b64 {%0, %1}, %2;" : "=f"(lo), "=f"(hi) : "l"(v));
}

// Shared memory: k-major tiles for compute phase; logits array reuses the
// same space for the fused top-k epilogue.
struct SMem {
    union {
        struct {
            float xs[KB][132];  // [k][row], stride 132 (528B: 16B-aligned, low store conflicts)
            float ws[KB][68];   // [k][expert], stride 68 (272B: 16B-aligned)
        } t;
        float logits[ROWS_CTA][65];  // stride 65 -> conflict-free row scans
    } u;
    float bias[NEXP];
};

__global__ __launch_bounds__(NTHREADS, 1)
void gating_kernel(const float* __restrict__ x, const float* __restrict__ Wm,
                   const float* __restrict__ bias_g, float* __restrict__ out,
                   int out_size)
{
    __shared__ SMem sm;
    const int tid = threadIdx.x;
    const int rowBase = blockIdx.x * ROWS_CTA;

    if (tid < NEXP) sm.bias[tid] = bias_g[tid];

    const int tx = tid & 15;        // expert group
    const int ty = tid >> 4;        // row group
    const int e0 = tx * 4;          // 4 experts per thread
    const int r0 = ty * 8;          // 8 rows per thread (4 packed row-pairs)

    // 16 packed f32x2 accumulators: [row-pair p][expert j]
    u64 acc[4][4];
#pragma unroll
    for (int p = 0; p < 4; p++)
#pragma unroll
        for (int j = 0; j < 4; j++) acc[p][j] = 0ULL;

    // register prefetch buffers (double buffering via regs)
    float4 px[4];
    float4 pw[2];

    // ---- prefetch chunk 0 ----
#pragma unroll
    for (int i = 0; i < 4; i++) {
        int idx = tid + i * NTHREADS;
        int r = idx >> 3, q = idx & 7;
        px[i] = *(const float4*)(x + (size_t)(rowBase + r) * DIM + q * 4);
    }
#pragma unroll
    for (int i = 0; i < 2; i++) {
        int idx = tid + i * NTHREADS;
        int e = idx >> 3, q = idx & 7;
        pw[i] = *(const float4*)(Wm + (size_t)e * DIM + q * 4);
    }

    for (int c = 0; c < NCHUNK; c++) {
        __syncthreads();  // previous chunk's compute done before overwriting tiles

        // ---- store prefetched regs -> smem (transposed to k-major) ----
#pragma unroll
        for (int i = 0; i < 4; i++) {
            int idx = tid + i * NTHREADS;
            int r = idx >> 3, q = idx & 7;
            sm.u.t.xs[q * 4 + 0][r] = px[i].x;
            sm.u.t.xs[q * 4 + 1][r] = px[i].y;
            sm.u.t.xs[q * 4 + 2][r] = px[i].z;
            sm.u.t.xs[q * 4 + 3][r] = px[i].w;
        }
#pragma unroll
        for (int i = 0; i < 2; i++) {
            int idx = tid + i * NTHREADS;
            int e = idx >> 3, q = idx & 7;
            sm.u.t.ws[q * 4 + 0][e] = pw[i].x;
            sm.u.t.ws[q * 4 + 1][e] = pw[i].y;
            sm.u.t.ws[q * 4 + 2][e] = pw[i].z;
            sm.u.t.ws[q * 4 + 3][e] = pw[i].w;
        }
        __syncthreads();

        // ---- issue LDG for next chunk (latency hidden behind compute) ----
        if (c + 1 < NCHUNK) {
            int k0n = (c + 1) * KB;
#pragma unroll
            for (int i = 0; i < 4; i++) {
                int idx = tid + i * NTHREADS;
                int r = idx >> 3, q = idx & 7;
                px[i] = *(const float4*)(x + (size_t)(rowBase + r) * DIM + k0n + q * 4);
            }
#pragma unroll
            for (int i = 0; i < 2; i++) {
                int idx = tid + i * NTHREADS;
                int e = idx >> 3, q = idx & 7;
                pw[i] = *(const float4*)(Wm + (size_t)e * DIM + k0n + q * 4);
            }
        }

        // ---- compute: chunk-local accumulators (limits sequential-sum error) ----
        u64 cl[4][4];
#pragma unroll
        for (int p = 0; p < 4; p++)
#pragma unroll
            for (int j = 0; j < 4; j++) cl[p][j] = 0ULL;

#pragma unroll
        for (int k = 0; k < KB; k++) {
            // row pairs from LDS.128: (r0,r0+1),(r0+2,r0+3),(r0+4,r0+5),(r0+6,r0+7)
            ulonglong2 av0 = *(const ulonglong2*)&sm.u.t.xs[k][r0];
            ulonglong2 av1 = *(const ulonglong2*)&sm.u.t.xs[k][r0 + 4];
            float4 bv = *(const float4*)&sm.u.t.ws[k][e0];
            u64 w0 = dup2(bv.x), w1 = dup2(bv.y), w2 = dup2(bv.z), w3 = dup2(bv.w);

            cl[0][0] = fma2(av0.x, w0, cl[0][0]);
            cl[0][1] = fma2(av0.x, w1, cl[0][1]);
            cl[0][2] = fma2(av0.x, w2, cl[0][2]);
            cl[0][3] = fma2(av0.x, w3, cl[0][3]);
            cl[1][0] = fma2(av0.y, w0, cl[1][0]);
            cl[1][1] = fma2(av0.y, w1, cl[1][1]);
            cl[1][2] = fma2(av0.y, w2, cl[1][2]);
            cl[1][3] = fma2(av0.y, w3, cl[1][3]);
            cl[2][0] = fma2(av1.x, w0, cl[2][0]);
            cl[2][1] = fma2(av1.x, w1, cl[2][1]);
            cl[2][2] = fma2(av1.x, w2, cl[2][2]);
            cl[2][3] = fma2(av1.x, w3, cl[2][3]);
            cl[3][0] = fma2(av1.y, w0, cl[3][0]);
            cl[3][1] = fma2(av1.y, w1, cl[3][1]);
            cl[3][2] = fma2(av1.y, w2, cl[3][2]);
            cl[3][3] = fma2(av1.y, w3, cl[3][3]);
        }

#pragma unroll
        for (int p = 0; p < 4; p++)
#pragma unroll
            for (int j = 0; j < 4; j++) acc[p][j] = add2(acc[p][j], cl[p][j]);
    }

    // ---- epilogue: logits -> smem (reusing tile space), fused top-2 ----
    __syncthreads();
#pragma unroll
    for (int p = 0; p < 4; p++)
#pragma unroll
        for (int j = 0; j < 4; j++) {
            float lo, hi;
            unpack2(acc[p][j], lo, hi);
            float bj = sm.bias[e0 + j];
            sm.u.logits[r0 + 2 * p][e0 + j]     = lo + bj;
            sm.u.logits[r0 + 2 * p + 1][e0 + j] = hi + bj;
        }
    __syncthreads();

    if (tid < ROWS_CTA) {
        // first-index-wins top-2 (matches jax.lax.top_k tie ordering)
        float v0 = -3.402823466e38f, v1 = -3.402823466e38f;
        int i0 = 0, i1 = 0;
#pragma unroll
        for (int e = 0; e < NEXP; e++) {
            float v = sm.u.logits[tid][e];
            if (v > v0) { v1 = v0; i1 = i0; v0 = v; i0 = e; }
            else if (v > v1) { v1 = v; i1 = e; }
        }
        // softmax over the two selected logits, max-subtracted like jax.nn.softmax
        float d  = expf(v1 - v0);
        float p0 = 1.0f / (1.0f + d);
        float p1 = d / (1.0f + d);

        int grow = rowBase + tid;
        float* orow = out + (size_t)grow * NEXP;
#pragma unroll
        for (int g = 0; g < NEXP / 4; g++) {
            float4 ov;
            int e = g * 4;
            ov.x = (e + 0 == i0) ? p0 : ((e + 0 == i1) ? p1 : 0.0f);
            ov.y = (e + 1 == i0) ? p0 : ((e + 1 == i1) ? p1 : 0.0f);
            ov.z = (e + 2 == i0) ? p0 : ((e + 2 == i1) ? p1 : 0.0f);
            ov.w = (e + 3 == i0) ? p0 : ((e + 3 == i1) ? p1 : 0.0f);
            *(float4*)(orow + e) = ov;
        }
        // second output (top_idx) appended after gates, if the buffer holds it
        if (out_size >= NROWS * (NEXP + 2)) {
            float* oidx = out + (size_t)NROWS * NEXP + (size_t)grow * 2;
            oidx[0] = (float)i0;
            oidx[1] = (float)i1;
        }
    }
}

extern "C" void kernel_launch(void* const* d_in, const int* in_sizes, int n_in,
                              void* d_out, int out_size) {
    // identify inputs by element count (robust to ordering): x, W, b, top_k
    const float* x = nullptr;
    const float* W = nullptr;
    const float* b = nullptr;
    for (int i = 0; i < n_in; i++) {
        if (in_sizes[i] == NROWS * DIM)      x = (const float*)d_in[i];
        else if (in_sizes[i] == NEXP * DIM)  W = (const float*)d_in[i];
        else if (in_sizes[i] == NEXP)        b = (const float*)d_in[i];
        // top_k (size 1) intentionally ignored: fixed k=2 per problem setup
    }
    gating_kernel<<<NROWS / ROWS_CTA, NTHREADS>>>(x, W, b, (float*)d_out, out_size);
}

// round 5
// speedup vs baseline: 3.1040x; 3.1040x over previous
#include <cuda_runtime.h>
#include <cuda_fp16.h>

typedef unsigned int u32;

#define NROWS    16384
#define DIM      4096
#define NEXP     64
#define KT       64
#define NCHUNK   (DIM / KT)
#define ROWS_CTA 128
#define NTH      256

#define WSCALE     4096.0f
#define INV_WSCALE (1.0f / 4096.0f)
#define RSC        2048.0f          // residual up-scale (2^11)
#define RINV       (1.0f / 2048.0f)

// smem layout (bytes): A tiles [stage][comp][128 rows][128B], B tiles [stage][comp][64 rows][128B]
#define A_COMP   16384
#define A_STAGE  32768
#define OFF_B    65536
#define B_COMP   8192
#define B_STAGE  16384
#define OFF_BIAS 98304
#define SMEM_BYTES 98560

#define SWZ(o) ((o) ^ (((o) >> 3) & 0x70))

// W pre-split: comp0 = fp16(W*4096), comp1 = fp16((W*4096 - comp0)*2048)
__device__ __half g_Wc[2][NEXP * DIM];

// ---------------- helpers ----------------
__device__ __forceinline__ u32 smem_u32(const void* p) {
    u32 a;
    asm("{ .reg .u64 t; cvta.to.shared.u64 t, %1; cvt.u32.u64 %0, t; }" : "=r"(a) : "l"(p));
    return a;
}

__device__ __forceinline__ void ldsm4(u32* r, u32 addr) {
    asm volatile("ldmatrix.sync.aligned.m8n8.x4.shared.b16 {%0,%1,%2,%3}, [%4];"
                 : "=r"(r[0]), "=r"(r[1]), "=r"(r[2]), "=r"(r[3]) : "r"(addr));
}

__device__ __forceinline__ void mma16816(float* d, const u32* a, u32 b0, u32 b1) {
    asm volatile(
        "mma.sync.aligned.m16n8k16.row.col.f32.f16.f16.f32 "
        "{%0,%1,%2,%3}, {%4,%5,%6,%7}, {%8,%9}, {%0,%1,%2,%3};"
        : "+f"(d[0]), "+f"(d[1]), "+f"(d[2]), "+f"(d[3])
        : "r"(a[0]), "r"(a[1]), "r"(a[2]), "r"(a[3]), "r"(b0), "r"(b1));
}

// split float4 -> hi fp16 comp + UP-SCALED fp16 residual comp (keeps residuals
// out of the fp16 subnormal range: this was the R4 accuracy bug)
__device__ __forceinline__ void split4(float4 v, uint2& h1, uint2& h2) {
    __half2 p0 = __floats2half2_rn(v.x, v.y);
    __half2 p1 = __floats2half2_rn(v.z, v.w);
    float2 f0 = __half22float2(p0);
    float2 f1 = __half22float2(p1);
    __half2 q0 = __floats2half2_rn((v.x - f0.x) * RSC, (v.y - f0.y) * RSC);
    __half2 q1 = __floats2half2_rn((v.z - f1.x) * RSC, (v.w - f1.y) * RSC);
    h1.x = reinterpret_cast<u32&>(p0);
    h1.y = reinterpret_cast<u32&>(p1);
    h2.x = reinterpret_cast<u32&>(q0);
    h2.y = reinterpret_cast<u32&>(q1);
}

// ---------------- prep: split scaled W into 2 fp16 components ----------------
__global__ void prep_kernel(const float* __restrict__ W) {
    int total = NEXP * DIM / 4;
    for (int idx = blockIdx.x * blockDim.x + threadIdx.x; idx < total;
         idx += gridDim.x * blockDim.x) {
        float4 v = ((const float4*)W)[idx];
        v.x *= WSCALE; v.y *= WSCALE; v.z *= WSCALE; v.w *= WSCALE;
        uint2 h1, h2;
        split4(v, h1, h2);
        ((uint2*)g_Wc[0])[idx] = h1;
        ((uint2*)g_Wc[1])[idx] = h2;
    }
}

// ---------------- main fused kernel ----------------
__global__ __launch_bounds__(NTH, 1)
void gating_mma_kernel(const float* __restrict__ x, const float* __restrict__ bias_g,
                       float* __restrict__ out, int out_size)
{
    extern __shared__ char smem[];
    const u32 sb = smem_u32(smem);
    const int tid = threadIdx.x;
    const int lane = tid & 31;
    const int warp = tid >> 5;
    const int rowBase = blockIdx.x * ROWS_CTA;
    const int mrow = (warp & 3) * 32;   // 4 warp-rows cover 128 M-rows
    const int ncol = (warp >> 2) * 32;  // 2 warp-cols cover 64 experts

    if (tid < NEXP) ((float*)(smem + OFF_BIAS))[tid] = bias_g[tid];

    // ---- register prefetch buffers ----
    float4 px[8];
    uint4  pw[4];

#pragma unroll
    for (int i = 0; i < 8; i++) {
        int idx = tid + i * NTH;
        int r = idx >> 4, q = idx & 15;
        px[i] = *(const float4*)(x + (size_t)(rowBase + r) * DIM + q * 4);
    }
#pragma unroll
    for (int i = 0; i < 4; i++) {
        int idx = tid + i * NTH;
        int comp = idx >> 9, rem = idx & 511, e = rem >> 3, q = rem & 7;
        pw[i] = *(const uint4*)(&g_Wc[comp][(size_t)e * DIM + q * 8]);
    }

    // main accumulator (x1*w1) and correction accumulator (x1*w2' + x2'*w1)
    float accm[2][4][4], accc[2][4][4];
#pragma unroll
    for (int mt = 0; mt < 2; mt++)
#pragma unroll
        for (int nt = 0; nt < 4; nt++)
#pragma unroll
            for (int j = 0; j < 4; j++) { accm[mt][nt][j] = 0.0f; accc[mt][nt][j] = 0.0f; }

    const int a_row  = (lane & 7) + 8 * ((lane >> 3) & 1);
    const int a_koff = (lane >> 4) * 8;
    const int b_e    = lane >> 2;
    const int b_k    = 2 * (lane & 3);

    for (int c = 0; c < NCHUNK; c++) {
        const int st = c & 1;
        char* As = smem + st * A_STAGE;
        char* Bs = smem + OFF_B + st * B_STAGE;

        // ---- STS: convert x to 2 fp16 comps, store W comps, swizzled ----
#pragma unroll
        for (int i = 0; i < 8; i++) {
            int idx = tid + i * NTH;
            int r = idx >> 4, q = idx & 15;
            uint2 h1, h2;
            split4(px[i], h1, h2);
            u32 off = SWZ((u32)(r * 128 + q * 8));
            *(uint2*)(As + off) = h1;
            *(uint2*)(As + A_COMP + off) = h2;
        }
#pragma unroll
        for (int i = 0; i < 4; i++) {
            int idx = tid + i * NTH;
            int comp = idx >> 9, rem = idx & 511, e = rem >> 3, q = rem & 7;
            u32 off = SWZ((u32)(e * 128 + q * 16));
            *(uint4*)(Bs + comp * B_COMP + off) = pw[i];
        }
        __syncthreads();

        // ---- prefetch next chunk into regs ----
        if (c + 1 < NCHUNK) {
            const float* xc = x + (size_t)rowBase * DIM + (c + 1) * KT;
#pragma unroll
            for (int i = 0; i < 8; i++) {
                int idx = tid + i * NTH;
                int r = idx >> 4, q = idx & 15;
                px[i] = *(const float4*)(xc + (size_t)r * DIM + q * 4);
            }
#pragma unroll
            for (int i = 0; i < 4; i++) {
                int idx = tid + i * NTH;
                int comp = idx >> 9, rem = idx & 511, e = rem >> 3, q = rem & 7;
                pw[i] = *(const uint4*)(&g_Wc[comp][(size_t)e * DIM + (c + 1) * KT + q * 8]);
            }
        }

        // ---- mma: shared A frags across passes; dual accumulators ----
        const u32 sA = sb + st * A_STAGE;
        const char* Bp1 = smem + OFF_B + st * B_STAGE;            // w1
        const char* Bp2 = Bp1 + B_COMP;                           // w2'
#pragma unroll
        for (int kc = 0; kc < 4; kc++) {
            u32 a1[2][4], a2[2][4];
#pragma unroll
            for (int mt = 0; mt < 2; mt++) {
                int row = mrow + mt * 16 + a_row;
                int ke = kc * 16 + a_koff;
                u32 off = SWZ((u32)(row * 128 + ke * 2));
                ldsm4(a1[mt], sA + off);
                ldsm4(a2[mt], sA + A_COMP + off);
            }
#pragma unroll
            for (int nt = 0; nt < 4; nt++) {
                int e = ncol + nt * 8 + b_e;
                int k = kc * 16 + b_k;
                u32 o0 = SWZ((u32)(e * 128 + k * 2));
                u32 o1 = SWZ((u32)(e * 128 + (k + 8) * 2));
                u32 b10 = *(const u32*)(Bp1 + o0);
                u32 b11 = *(const u32*)(Bp1 + o1);
                u32 b20 = *(const u32*)(Bp2 + o0);
                u32 b21 = *(const u32*)(Bp2 + o1);
                mma16816(accm[0][nt], a1[0], b10, b11);
                mma16816(accm[1][nt], a1[1], b10, b11);
                mma16816(accc[0][nt], a1[0], b20, b21);
                mma16816(accc[1][nt], a1[1], b20, b21);
                mma16816(accc[0][nt], a2[0], b10, b11);
                mma16816(accc[1][nt], a2[1], b10, b11);
            }
        }
    }

    // ---- epilogue: combine accumulators, logits -> smem overlay, fused top-2 ----
    __syncthreads();
    float (*lg)[66] = (float(*)[66])smem;
#pragma unroll
    for (int mt = 0; mt < 2; mt++)
#pragma unroll
        for (int nt = 0; nt < 4; nt++) {
            int r0 = mrow + mt * 16 + (lane >> 2);
            int cb = ncol + nt * 8 + 2 * (lane & 3);
            float c0 = fmaf(accc[mt][nt][0], RINV, accm[mt][nt][0]);
            float c1 = fmaf(accc[mt][nt][1], RINV, accm[mt][nt][1]);
            float c2 = fmaf(accc[mt][nt][2], RINV, accm[mt][nt][2]);
            float c3 = fmaf(accc[mt][nt][3], RINV, accm[mt][nt][3]);
            *(float2*)&lg[r0][cb]     = make_float2(c0, c1);
            *(float2*)&lg[r0 + 8][cb] = make_float2(c2, c3);
        }
    __syncthreads();

    if (tid < ROWS_CTA) {
        const float* bs = (const float*)(smem + OFF_BIAS);
        float v0 = -3.402823466e38f, v1 = -3.402823466e38f;
        int i0 = 0, i1 = 0;
#pragma unroll
        for (int e = 0; e < NEXP; e++) {
            float v = fmaf(lg[tid][e], INV_WSCALE, bs[e]);
            if (v > v0) { v1 = v0; i1 = i0; v0 = v; i0 = e; }
            else if (v > v1) { v1 = v; i1 = e; }
        }
        float d  = expf(v1 - v0);
        float p0 = 1.0f / (1.0f + d);
        float p1 = d / (1.0f + d);

        int grow = rowBase + tid;
        float* orow = out + (size_t)grow * NEXP;
#pragma unroll
        for (int g = 0; g < NEXP / 4; g++) {
            float4 ov;
            int e = g * 4;
            ov.x = (e + 0 == i0) ? p0 : ((e + 0 == i1) ? p1 : 0.0f);
            ov.y = (e + 1 == i0) ? p0 : ((e + 1 == i1) ? p1 : 0.0f);
            ov.z = (e + 2 == i0) ? p0 : ((e + 2 == i1) ? p1 : 0.0f);
            ov.w = (e + 3 == i0) ? p0 : ((e + 3 == i1) ? p1 : 0.0f);
            *(float4*)(orow + e) = ov;
        }
        if (out_size >= NROWS * (NEXP + 2)) {
            float* oidx = out + (size_t)NROWS * NEXP + (size_t)grow * 2;
            oidx[0] = (float)i0;
            oidx[1] = (float)i1;
        }
    }
}

extern "C" void kernel_launch(void* const* d_in, const int* in_sizes, int n_in,
                              void* d_out, int out_size) {
    const float* x = nullptr;
    const float* W = nullptr;
    const float* b = nullptr;
    for (int i = 0; i < n_in; i++) {
        if (in_sizes[i] == NROWS * DIM)      x = (const float*)d_in[i];
        else if (in_sizes[i] == NEXP * DIM)  W = (const float*)d_in[i];
        else if (in_sizes[i] == NEXP)        b = (const float*)d_in[i];
    }
    cudaFuncSetAttribute(gating_mma_kernel, cudaFuncAttributeMaxDynamicSharedMemorySize,
                         SMEM_BYTES);
    prep_kernel<<<128, 256>>>(W);
    gating_mma_kernel<<<NROWS / ROWS_CTA, NTH, SMEM_BYTES>>>(x, b, (float*)d_out, out_size);
}